// round 14
// baseline (speedup 1.0000x reference)
#include <cuda_runtime.h>
#include <cuda_fp16.h>
#include <cstdint>

// ---------------------------------------------------------------------------
// MoE top-2/8, sparse routing. GEMM: mma.sync.m16n8k16.f16 (fp32 accum),
// ldmatrix, 3-stage cp.async pipeline (unrolled x3), CTA 128x128, 2 CTAs/SM.
// R14: compact tile table built in scatter's last block (GEMM grid 16384->4160,
// counters self-reset per run); transpose+xgate merged into one prep kernel.
// ---------------------------------------------------------------------------

#define NTOK   32768
#define DIN    1024
#define DOUT   1024
#define NEXP   8
#define NASSIGN (NTOK * 2)
#define TILE_M 128
#define MAXT   520                 // max total tiles: 512 + 8
#define KC     64
#define NB     128
#define NNB    (DOUT / NB)         // 8
#define NCHUNK (DIN / KC)          // 16

// ---------------- scratch (device globals: allocation-free) ----------------
__device__ int    g_topE[NASSIGN];
__device__ float  g_topG[NASSIGN];
__device__ int    g_cnt[NEXP];
__device__ int    g_cur[NEXP];
__device__ int    g_done;
__device__ int    g_numTiles;
__device__ int    g_tileE[MAXT];
__device__ int    g_tileBase[MAXT];     // local offset within expert segment
__device__ int    g_tileRows[MAXT];
__device__ int    g_tok[NEXP * NTOK];
__device__ int    g_ki[NEXP * NTOK];
__device__ __half g_xh[(size_t)NTOK * DIN];            // fp16 x (64 MB)
__device__ __half g_Bh[(size_t)NEXP * DOUT * DIN];     // W^T fp16 [e][n][k] (16 MB)
__device__ __half g_h[(size_t)NASSIGN * DOUT];         // GELU(xW+b) fp16 (128 MB)

// ---------------------------- helpers ---------------------------------------
__device__ __forceinline__ float gelu_exact(float v) {
    return 0.5f * v * (1.0f + erff(v * 0.70710678118654752f));
}
__device__ __forceinline__ uint32_t smem_u32(const void* p) {
    uint32_t a;
    asm("{ .reg .u64 t; cvta.to.shared.u64 t, %1; cvt.u32.u64 %0, t; }"
        : "=r"(a) : "l"(p));
    return a;
}
__device__ __forceinline__ uint32_t sw128(uint32_t o) { return o ^ ((o >> 3) & 0x70); }

__device__ __forceinline__ void cpa16(uint32_t saddr, const void* g) {
    asm volatile("cp.async.cg.shared.global [%0], [%1], 16;\n"
                 :: "r"(saddr), "l"(g));
}
#define CPA_COMMIT() asm volatile("cp.async.commit_group;\n" ::: "memory")
#define CPA_WAIT1()  asm volatile("cp.async.wait_group 1;\n" ::: "memory")

__device__ __forceinline__ void ldsm4(uint32_t& r0, uint32_t& r1,
                                      uint32_t& r2, uint32_t& r3, uint32_t a) {
    asm volatile("ldmatrix.sync.aligned.m8n8.x4.shared.b16 {%0,%1,%2,%3}, [%4];"
                 : "=r"(r0), "=r"(r1), "=r"(r2), "=r"(r3) : "r"(a));
}
__device__ __forceinline__ void mma16816(float (&c)[4],
                                         uint32_t a0, uint32_t a1,
                                         uint32_t a2, uint32_t a3,
                                         uint32_t b0, uint32_t b1) {
    asm volatile(
        "mma.sync.aligned.m16n8k16.row.col.f32.f16.f16.f32 "
        "{%0,%1,%2,%3},{%4,%5,%6,%7},{%8,%9},{%0,%1,%2,%3};\n"
        : "+f"(c[0]), "+f"(c[1]), "+f"(c[2]), "+f"(c[3])
        : "r"(a0), "r"(a1), "r"(a2), "r"(a3), "r"(b0), "r"(b1));
}

// ------------------------------- kernels -------------------------------------

// Merged prep: blocks [0,8192) transpose We -> g_Bh (fp16, K-major);
// blocks [8192,9216) do fused x->fp16 + fp32 gating (4 tokens/warp).
// Counters are NOT zeroed here — scatter's tail zeroes them for the next run
// (module-load zero-init covers the first run).
__global__ void __launch_bounds__(256)
prep_kernel(const float* __restrict__ We,
            const float* __restrict__ x,
            const float* __restrict__ Wg,
            const float* __restrict__ bg) {
    __shared__ float smem_u[NEXP][DIN];   // 32 KB; transpose uses a subset
    int b   = blockIdx.x;
    int tid = threadIdx.x;

    if (b < 8192) {
        // ---- transpose part ----
        float (*tile)[33] = (float(*)[33])smem_u;   // 32*33 floats = 4224 B
        int e   = b >> 10;
        int rem = b & 1023;
        int kb  = (rem >> 5) * 32;
        int nbb = (rem & 31) * 32;
        int tx = tid & 31, ty = tid >> 5;
        const float* src = We + ((size_t)e * DIN + kb) * DOUT + nbb;
#pragma unroll
        for (int i = 0; i < 32; i += 8)
            tile[ty + i][tx] = src[(size_t)(ty + i) * DOUT + tx];
        __syncthreads();
        __half* dst = g_Bh + ((size_t)e * DOUT + nbb) * DIN + kb;
#pragma unroll
        for (int i = 0; i < 32; i += 8)
            dst[(size_t)(ty + i) * DIN + tx] = __float2half_rn(tile[tx][ty + i]);
        return;
    }

    // ---- xgate part ----
    float (*sW)[DIN] = smem_u;
    for (int idx = tid; idx < DIN * NEXP; idx += 256) {
        int i = idx >> 3, e = idx & 7;
        sW[e][i] = Wg[idx];
    }
    __syncthreads();

    int wid = tid >> 5, lane = tid & 31;
    int n0 = (b - 8192) * 32 + wid * 4;

    const float4* xr = (const float4*)(x + (size_t)n0 * DIN);
    uint2*        xo = (uint2*)(g_xh + (size_t)n0 * DIN);

    float acc[4][NEXP];
#pragma unroll
    for (int t = 0; t < 4; t++)
#pragma unroll
        for (int e = 0; e < NEXP; e++) acc[t][e] = 0.f;

#pragma unroll
    for (int j = 0; j < 8; j++) {
        int c = lane + 32 * j;
        float4 xv[4];
#pragma unroll
        for (int t = 0; t < 4; t++) {
            xv[t] = xr[t * 256 + c];
            __half2 h01 = __floats2half2_rn(xv[t].x, xv[t].y);
            __half2 h23 = __floats2half2_rn(xv[t].z, xv[t].w);
            uint2 o;
            o.x = *(uint32_t*)&h01;
            o.y = *(uint32_t*)&h23;
            xo[t * 256 + c] = o;
        }
#pragma unroll
        for (int e = 0; e < NEXP; e++) {
            float4 wv = ((const float4*)sW[e])[c];
#pragma unroll
            for (int t = 0; t < 4; t++)
                acc[t][e] += xv[t].x * wv.x + xv[t].y * wv.y
                           + xv[t].z * wv.z + xv[t].w * wv.w;
        }
    }
#pragma unroll
    for (int off = 16; off > 0; off >>= 1)
#pragma unroll
        for (int t = 0; t < 4; t++)
#pragma unroll
            for (int e = 0; e < NEXP; e++)
                acc[t][e] += __shfl_down_sync(0xffffffffu, acc[t][e], off);

    if (lane == 0) {
#pragma unroll
        for (int t = 0; t < 4; t++) {
            int n = n0 + t;
            float l[NEXP];
#pragma unroll
            for (int e = 0; e < NEXP; e++) l[e] = tanhf(acc[t][e] + bg[e]);
            int i1 = 0; float b1 = l[0];
#pragma unroll
            for (int e = 1; e < NEXP; e++) if (l[e] > b1) { b1 = l[e]; i1 = e; }
            int i2 = -1; float b2 = -1e30f;
#pragma unroll
            for (int e = 0; e < NEXP; e++)
                if (e != i1 && l[e] > b2) { b2 = l[e]; i2 = e; }
            float ex  = expf(b2 - b1);
            float inv = 1.0f / (1.0f + ex);
            g_topE[n * 2 + 0] = i1;  g_topG[n * 2 + 0] = inv;
            g_topE[n * 2 + 1] = i2;  g_topG[n * 2 + 1] = ex * inv;
            atomicAdd(&g_cnt[i1], 1);
            atomicAdd(&g_cnt[i2], 1);
        }
    }
}

// Warp-aggregated scatter; LAST block builds the compact tile table and
// resets counters for the next graph replay.
__global__ void __launch_bounds__(256)
scatter_kernel() {
    int idx  = blockIdx.x * 256 + threadIdx.x;
    int lane = threadIdx.x & 31;
    int e = g_topE[idx];
    unsigned mask = __match_any_sync(0xffffffffu, e);
    int leader = __ffs(mask) - 1;
    int rank   = __popc(mask & ((1u << lane) - 1));
    int basep = 0;
    if (lane == leader) basep = atomicAdd(&g_cur[e], __popc(mask));
    basep = __shfl_sync(0xffffffffu, basep, leader);
    int s = e * NTOK + basep + rank;
    g_tok[s] = idx >> 1;
    g_ki[s]  = idx & 1;

    // ---- last-block tail: tile table + counter reset ----
    __shared__ int sLast;
    __shared__ int sOffE[NEXP];
    __shared__ int sCntE[NEXP];
    __threadfence();
    if (threadIdx.x == 0)
        sLast = (atomicAdd(&g_done, 1) == (int)gridDim.x - 1);
    __syncthreads();
    if (!sLast) return;

    if (threadIdx.x == 0) {
        g_done = 0;
        int nt = 0;
        for (int ee = 0; ee < NEXP; ee++) {
            int c = g_cnt[ee];
            sCntE[ee] = c;
            sOffE[ee] = nt;
            nt += (c + TILE_M - 1) / TILE_M;
        }
        g_numTiles = nt;
    }
    __syncthreads();
#pragma unroll
    for (int ee = 0; ee < NEXP; ee++) {
        int c   = sCntE[ee];
        int ntE = (c + TILE_M - 1) / TILE_M;
        for (int t = threadIdx.x; t < ntE; t += 256) {
            int ti = sOffE[ee] + t;
            g_tileE[ti]    = ee;
            g_tileBase[ti] = t * TILE_M;
            int r = c - t * TILE_M;
            g_tileRows[ti] = r < TILE_M ? r : TILE_M;
        }
    }
    if (threadIdx.x < NEXP) {
        g_cnt[threadIdx.x] = 0;     // reset for next run
        g_cur[threadIdx.x] = 0;
    }
}

// --------------------------- grouped GEMM ------------------------------------
// Compact grid: MAXT x 8 nb = 4160 CTAs; CTAs beyond g_numTiles exit (~<=64).
// CTA: 128x128, 256 threads = 8 warps (4M x 2N), warp tile 32x64.
// K=1024 in 16 chunks of 64, 3-stage cp.async manually unrolled x3.

constexpr int A_BYTES = TILE_M * KC * 2;   // 16 KB
constexpr int B_BYTES = NB * KC * 2;       // 16 KB
constexpr int STAGE   = A_BYTES + B_BYTES; // 32 KB
constexpr int DYN_SMEM = 3 * STAGE + 1024; // 99 KB -> 2 CTAs/SM

extern __shared__ __align__(1024) char dsm[];

__global__ void __launch_bounds__(256, 2)
moe_gemm_kernel(const float* __restrict__ be) {
    int bx = blockIdx.x;
    int ti = bx >> 3;
    int nb = bx & 7;
    if (ti >= g_numTiles) return;

    int e    = g_tileE[ti];
    int base = g_tileBase[ti];
    int rows = g_tileRows[ti];

    __shared__ int sTok[TILE_M];
    __shared__ int sKi[TILE_M];

    int tid  = threadIdx.x;
    int lane = tid & 31;
    int wid  = tid >> 5;
    int warpM = wid & 3;
    int warpN = wid >> 2;

    const int* segT = g_tok + e * NTOK + base;
    const int* segK = g_ki  + e * NTOK + base;
    if (tid < TILE_M) {
        int i = tid;
        int j = (i < rows ? i : rows - 1);
        sTok[i] = segT[j];
        sKi[i]  = segK[j];
    }
    __syncthreads();

    uint32_t sbase = (smem_u32(dsm) + 1023) & ~1023u;
    const __half* btBase = g_Bh + ((size_t)e * DOUT + nb * NB) * DIN;

    int r0 = tid >> 3;
    int ch = tid & 7;
    const __half* aP0 = g_xh + (size_t)sTok[r0 +  0] * DIN + ch * 8;
    const __half* aP1 = g_xh + (size_t)sTok[r0 + 32] * DIN + ch * 8;
    const __half* aP2 = g_xh + (size_t)sTok[r0 + 64] * DIN + ch * 8;
    const __half* aP3 = g_xh + (size_t)sTok[r0 + 96] * DIN + ch * 8;
    const __half* bP  = btBase + (size_t)r0 * DIN + ch * 8;
    uint32_t sOff = sw128((uint32_t)(r0 * 128 + ch * 16));

    float c[2][8][4];
#pragma unroll
    for (int mt = 0; mt < 2; mt++)
#pragma unroll
        for (int nt = 0; nt < 8; nt++)
#pragma unroll
            for (int q = 0; q < 4; q++) c[mt][nt][q] = 0.f;

    auto load_chunk = [&](uint32_t buf, int kg) {
        uint32_t aBuf = buf + sOff;
        uint32_t bBuf = buf + A_BYTES + sOff;
        cpa16(aBuf,         aP0 + kg);
        cpa16(aBuf +  4096, aP1 + kg);
        cpa16(aBuf +  8192, aP2 + kg);
        cpa16(aBuf + 12288, aP3 + kg);
        cpa16(bBuf,         bP + kg);
        cpa16(bBuf +  4096, bP + 32 * DIN + kg);
        cpa16(bBuf +  8192, bP + 64 * DIN + kg);
        cpa16(bBuf + 12288, bP + 96 * DIN + kg);
    };

    load_chunk(sbase, 0);
    CPA_COMMIT();
    load_chunk(sbase + STAGE, KC);
    CPA_COMMIT();

    uint32_t aRowOff = (uint32_t)((warpM * 32 + (lane & 15)) * 128 + ((lane >> 4) << 4));
    uint32_t bRowOff = (uint32_t)((warpN * 64 + (lane & 7) + ((lane >> 4) << 3)) * 128
                                  + (((lane >> 3) & 1) << 4));
    uint32_t aSwK[4], bSwK[4];
#pragma unroll
    for (int s4 = 0; s4 < 4; s4++) {
        aSwK[s4] = sw128(aRowOff + 32u * s4);
        bSwK[s4] = sw128(bRowOff + 32u * s4);
    }

    auto chunk_body = [&](int ck, int bufSel) {
        CPA_WAIT1();
        __syncthreads();
        if (ck + 2 < NCHUNK) {
            int nxt = (ck + 2) % 3;
            load_chunk(sbase + nxt * STAGE, (ck + 2) * KC);
        }
        CPA_COMMIT();

        uint32_t stageA = sbase + bufSel * STAGE;
        uint32_t stageB = stageA + A_BYTES;
#pragma unroll
        for (int s4 = 0; s4 < 4; s4++) {
            uint32_t aA = stageA + aSwK[s4];
            uint32_t bA = stageB + bSwK[s4];
            uint32_t aF[2][4], bF[4][4];
            ldsm4(aF[0][0], aF[0][1], aF[0][2], aF[0][3], aA);
            ldsm4(aF[1][0], aF[1][1], aF[1][2], aF[1][3], aA + 2048);
            ldsm4(bF[0][0], bF[0][1], bF[0][2], bF[0][3], bA);
            ldsm4(bF[1][0], bF[1][1], bF[1][2], bF[1][3], bA + 2048);
            ldsm4(bF[2][0], bF[2][1], bF[2][2], bF[2][3], bA + 4096);
            ldsm4(bF[3][0], bF[3][1], bF[3][2], bF[3][3], bA + 6144);
#pragma unroll
            for (int bt = 0; bt < 4; bt++) {
                mma16816(c[0][2 * bt],     aF[0][0], aF[0][1], aF[0][2], aF[0][3],
                         bF[bt][0], bF[bt][1]);
                mma16816(c[0][2 * bt + 1], aF[0][0], aF[0][1], aF[0][2], aF[0][3],
                         bF[bt][2], bF[bt][3]);
                mma16816(c[1][2 * bt],     aF[1][0], aF[1][1], aF[1][2], aF[1][3],
                         bF[bt][0], bF[bt][1]);
                mma16816(c[1][2 * bt + 1], aF[1][0], aF[1][1], aF[1][2], aF[1][3],
                         bF[bt][2], bF[bt][3]);
            }
        }
    };

#pragma unroll
    for (int c3 = 0; c3 < 15; c3 += 3) {
        chunk_body(c3,     0);
        chunk_body(c3 + 1, 1);
        chunk_body(c3 + 2, 2);
    }
    chunk_body(15, 0);

    // ---------------- epilogue: bias + GELU, write h (fp16) -------------------
    int la4 = lane >> 2, lq = lane & 3;
    int gcol0 = nb * NB + warpN * 64;

#pragma unroll
    for (int mt = 0; mt < 2; mt++) {
        int rr0 = warpM * 32 + mt * 16 + la4;
        int rr1 = rr0 + 8;
        bool v0 = rr0 < rows, v1 = rr1 < rows;
        __half* d0 = g_h + (((size_t)sTok[rr0] * 2 + sKi[rr0]) << 10);
        __half* d1 = g_h + (((size_t)sTok[rr1] * 2 + sKi[rr1]) << 10);
#pragma unroll
        for (int nt = 0; nt < 8; nt++) {
            int col = gcol0 + nt * 8 + 2 * lq;
            float2 bv = *(const float2*)(be + (size_t)e * DOUT + col);
            if (v0) {
                __half2 o = __floats2half2_rn(gelu_exact(c[mt][nt][0] + bv.x),
                                              gelu_exact(c[mt][nt][1] + bv.y));
                *(__half2*)(d0 + col) = o;
            }
            if (v1) {
                __half2 o = __floats2half2_rn(gelu_exact(c[mt][nt][2] + bv.x),
                                              gelu_exact(c[mt][nt][3] + bv.y));
                *(__half2*)(d1 + col) = o;
            }
        }
    }
}

// --------------- pass 2: LayerNorm + gamma/beta + gate + combine -------------
// 256 threads, 128 tokens/block (8 warps x 16 tokens serial); gamma/beta
// staged once per block in 64 KB smem.
__global__ void __launch_bounds__(256)
ln_combine_kernel(const float* __restrict__ gamma,
                  const float* __restrict__ beta,
                  float* __restrict__ out) {
    float* gsm = (float*)dsm;            // [0:8192) gamma, [8192:16384) beta
    int tid = threadIdx.x;
    for (int i = tid; i < NEXP * DOUT; i += 256) {
        gsm[i]               = gamma[i];
        gsm[NEXP * DOUT + i] = beta[i];
    }
    __syncthreads();

    int wid = tid >> 5, lane = tid & 31;
    const float4* g4 = (const float4*)gsm;
    const float4* b4 = g4 + (NEXP * DOUT / 4);

    for (int t = 0; t < 16; t++) {
        int n = blockIdx.x * 128 + wid * 16 + t;

        const uint2* h0p = (const uint2*)(g_h + ((size_t)n * 2)     * DOUT);
        const uint2* h1p = (const uint2*)(g_h + ((size_t)n * 2 + 1) * DOUT);

        uint2 u0[8], u1[8];
        float s0 = 0.f, q0 = 0.f, s1 = 0.f, q1 = 0.f;
#pragma unroll
        for (int k = 0; k < 8; k++) {
            int cc = lane + 32 * k;
            u0[k] = h0p[cc];
            u1[k] = h1p[cc];
            float2 a0 = __half22float2(*(__half2*)&u0[k].x);
            float2 c0 = __half22float2(*(__half2*)&u0[k].y);
            float2 a1 = __half22float2(*(__half2*)&u1[k].x);
            float2 c1 = __half22float2(*(__half2*)&u1[k].y);
            s0 += a0.x + a0.y + c0.x + c0.y;
            q0 += a0.x * a0.x + a0.y * a0.y + c0.x * c0.x + c0.y * c0.y;
            s1 += a1.x + a1.y + c1.x + c1.y;
            q1 += a1.x * a1.x + a1.y * a1.y + c1.x * c1.x + c1.y * c1.y;
        }
#pragma unroll
        for (int off = 16; off > 0; off >>= 1) {
            s0 += __shfl_xor_sync(0xffffffffu, s0, off);
            q0 += __shfl_xor_sync(0xffffffffu, q0, off);
            s1 += __shfl_xor_sync(0xffffffffu, s1, off);
            q1 += __shfl_xor_sync(0xffffffffu, q1, off);
        }
        float m0 = s0 * (1.f / DOUT), m1 = s1 * (1.f / DOUT);
        float r0 = rsqrtf(q0 * (1.f / DOUT) - m0 * m0 + 1e-5f);
        float r1 = rsqrtf(q1 * (1.f / DOUT) - m1 * m1 + 1e-5f);

        int e0 = g_topE[n * 2 + 0], e1 = g_topE[n * 2 + 1];
        float gg0 = g_topG[n * 2 + 0], gg1 = g_topG[n * 2 + 1];
        int gi0 = e0 * (DOUT / 4), gi1 = e1 * (DOUT / 4);

        float4* op = (float4*)out + (size_t)n * (DOUT / 4);
#pragma unroll
        for (int k = 0; k < 8; k++) {
            int cc = lane + 32 * k;
            float2 a0 = __half22float2(*(__half2*)&u0[k].x);
            float2 c0 = __half22float2(*(__half2*)&u0[k].y);
            float2 a1 = __half22float2(*(__half2*)&u1[k].x);
            float2 c1 = __half22float2(*(__half2*)&u1[k].y);
            float4 ga = g4[gi0 + cc], ba = b4[gi0 + cc];
            float4 gb = g4[gi1 + cc], bb = b4[gi1 + cc];
            float4 o;
            o.x = ((a0.x - m0) * r0 * ga.x + ba.x) * gg0 + ((a1.x - m1) * r1 * gb.x + bb.x) * gg1;
            o.y = ((a0.y - m0) * r0 * ga.y + ba.y) * gg0 + ((a1.y - m1) * r1 * gb.y + bb.y) * gg1;
            o.z = ((c0.x - m0) * r0 * ga.z + ba.z) * gg0 + ((c1.x - m1) * r1 * gb.z + bb.z) * gg1;
            o.w = ((c0.y - m0) * r0 * ga.w + ba.w) * gg0 + ((c1.y - m1) * r1 * gb.w + bb.w) * gg1;
            op[cc] = o;
        }
    }
}

// ------------------------------- launcher -----------------------------------
extern "C" void kernel_launch(void* const* d_in, const int* in_sizes, int n_in,
                              void* d_out, int out_size) {
    const float* x     = (const float*)d_in[0];
    const float* Wg    = (const float*)d_in[1];
    const float* bg    = (const float*)d_in[2];
    const float* We    = (const float*)d_in[3];
    const float* be    = (const float*)d_in[4];
    const float* gamma = (const float*)d_in[5];
    const float* beta  = (const float*)d_in[6];
    float* out = (float*)d_out;

    cudaFuncSetAttribute(moe_gemm_kernel,
                         cudaFuncAttributeMaxDynamicSharedMemorySize, DYN_SMEM);
    cudaFuncSetAttribute(ln_combine_kernel,
                         cudaFuncAttributeMaxDynamicSharedMemorySize, 65536);

    prep_kernel<<<8192 + NTOK / 32, 256>>>(We, x, Wg, bg);   // transpose + xgate
    scatter_kernel<<<NASSIGN / 256, 256>>>();                // + tile table tail
    moe_gemm_kernel<<<MAXT * NNB, 256, DYN_SMEM>>>(be);
    ln_combine_kernel<<<NTOK / 128, 256, 65536>>>(gamma, beta, out);
}

// round 15
// speedup vs baseline: 1.0211x; 1.0211x over previous
#include <cuda_runtime.h>
#include <cuda_fp16.h>
#include <cstdint>

// ---------------------------------------------------------------------------
// MoE top-2/8, sparse routing. GEMM: mma.sync.m16n8k16.f16 (fp32 accum),
// ldmatrix, 3-stage cp.async pipeline (unrolled x3), CTA 128x128, 2 CTAs/SM.
// R15: full revert to R13 structure (merge + tile table regressed); single
// change: ln_combine 64 tokens/block (grid 512) for better SM load spread.
// ---------------------------------------------------------------------------

#define NTOK   32768
#define DIN    1024
#define DOUT   1024
#define NEXP   8
#define NASSIGN (NTOK * 2)
#define TILE_M 128
#define TPE    (NTOK / TILE_M)     // 256 max tiles per expert
#define KC     64
#define NB     128
#define NNB    (DOUT / NB)         // 8
#define NCHUNK (DIN / KC)          // 16

// ---------------- scratch (device globals: allocation-free) ----------------
__device__ int    g_topE[NASSIGN];
__device__ float  g_topG[NASSIGN];
__device__ int    g_cnt[NEXP];
__device__ int    g_cur[NEXP];
__device__ int    g_tok[NEXP * NTOK];
__device__ int    g_ki[NEXP * NTOK];
__device__ __half g_xh[(size_t)NTOK * DIN];            // fp16 x (64 MB)
__device__ __half g_Bh[(size_t)NEXP * DOUT * DIN];     // W^T fp16 [e][n][k] (16 MB)
__device__ __half g_h[(size_t)NASSIGN * DOUT];         // GELU(xW+b) fp16 (128 MB)

// ---------------------------- helpers ---------------------------------------
__device__ __forceinline__ float gelu_exact(float v) {
    return 0.5f * v * (1.0f + erff(v * 0.70710678118654752f));
}
__device__ __forceinline__ uint32_t smem_u32(const void* p) {
    uint32_t a;
    asm("{ .reg .u64 t; cvta.to.shared.u64 t, %1; cvt.u32.u64 %0, t; }"
        : "=r"(a) : "l"(p));
    return a;
}
__device__ __forceinline__ uint32_t sw128(uint32_t o) { return o ^ ((o >> 3) & 0x70); }

__device__ __forceinline__ void cpa16(uint32_t saddr, const void* g) {
    asm volatile("cp.async.cg.shared.global [%0], [%1], 16;\n"
                 :: "r"(saddr), "l"(g));
}
#define CPA_COMMIT() asm volatile("cp.async.commit_group;\n" ::: "memory")
#define CPA_WAIT1()  asm volatile("cp.async.wait_group 1;\n" ::: "memory")

__device__ __forceinline__ void ldsm4(uint32_t& r0, uint32_t& r1,
                                      uint32_t& r2, uint32_t& r3, uint32_t a) {
    asm volatile("ldmatrix.sync.aligned.m8n8.x4.shared.b16 {%0,%1,%2,%3}, [%4];"
                 : "=r"(r0), "=r"(r1), "=r"(r2), "=r"(r3) : "r"(a));
}
__device__ __forceinline__ void mma16816(float (&c)[4],
                                         uint32_t a0, uint32_t a1,
                                         uint32_t a2, uint32_t a3,
                                         uint32_t b0, uint32_t b1) {
    asm volatile(
        "mma.sync.aligned.m16n8k16.row.col.f32.f16.f16.f32 "
        "{%0,%1,%2,%3},{%4,%5,%6,%7},{%8,%9},{%0,%1,%2,%3};\n"
        : "+f"(c[0]), "+f"(c[1]), "+f"(c[2]), "+f"(c[3])
        : "r"(a0), "r"(a1), "r"(a2), "r"(a3), "r"(b0), "r"(b1));
}

// ------------------------------- kernels -------------------------------------

// We[e][k][n] (fp32) -> g_Bh[e][n][k] (fp16); block(0,0,0) also zeroes counters.
__global__ void transpose_kernel(const float* __restrict__ We) {
    if (blockIdx.x == 0 && blockIdx.y == 0 && blockIdx.z == 0 &&
        threadIdx.y == 0 && threadIdx.x < NEXP) {
        g_cnt[threadIdx.x] = 0;
        g_cur[threadIdx.x] = 0;
    }
    __shared__ float tile[32][33];
    int e  = blockIdx.z;
    int kb = blockIdx.y * 32;
    int nb = blockIdx.x * 32;
    const float* src = We + ((size_t)e * DIN + kb) * DOUT + nb;
#pragma unroll
    for (int i = 0; i < 32; i += 8)
        tile[threadIdx.y + i][threadIdx.x] = src[(size_t)(threadIdx.y + i) * DOUT + threadIdx.x];
    __syncthreads();
    __half* dst = g_Bh + ((size_t)e * DOUT + nb) * DIN + kb;
#pragma unroll
    for (int i = 0; i < 32; i += 8)
        dst[(size_t)(threadIdx.y + i) * DIN + threadIdx.x] =
            __float2half_rn(tile[threadIdx.x][threadIdx.y + i]);
}

// --------------------- fused x->fp16 + gating (fp32) -------------------------
// 4 tokens per warp (Wg smem read reused 4x). No scatter here (R11 lesson).
__global__ void __launch_bounds__(256)
xgate_kernel(const float* __restrict__ x,
             const float* __restrict__ Wg,
             const float* __restrict__ bg) {
    __shared__ float sW[NEXP][DIN];   // 32 KB transposed: sW[e][i]
    int tid = threadIdx.x;
    for (int idx = tid; idx < DIN * NEXP; idx += 256) {
        int i = idx >> 3, e = idx & 7;
        sW[e][i] = Wg[idx];
    }
    __syncthreads();

    int wid = tid >> 5, lane = tid & 31;
    int n0 = blockIdx.x * 32 + wid * 4;

    const float4* xr = (const float4*)(x + (size_t)n0 * DIN);
    uint2*        xo = (uint2*)(g_xh + (size_t)n0 * DIN);

    float acc[4][NEXP];
#pragma unroll
    for (int t = 0; t < 4; t++)
#pragma unroll
        for (int e = 0; e < NEXP; e++) acc[t][e] = 0.f;

#pragma unroll
    for (int j = 0; j < 8; j++) {
        int c = lane + 32 * j;
        float4 xv[4];
#pragma unroll
        for (int t = 0; t < 4; t++) {
            xv[t] = xr[t * 256 + c];
            __half2 h01 = __floats2half2_rn(xv[t].x, xv[t].y);
            __half2 h23 = __floats2half2_rn(xv[t].z, xv[t].w);
            uint2 o;
            o.x = *(uint32_t*)&h01;
            o.y = *(uint32_t*)&h23;
            xo[t * 256 + c] = o;
        }
#pragma unroll
        for (int e = 0; e < NEXP; e++) {
            float4 wv = ((const float4*)sW[e])[c];
#pragma unroll
            for (int t = 0; t < 4; t++)
                acc[t][e] += xv[t].x * wv.x + xv[t].y * wv.y
                           + xv[t].z * wv.z + xv[t].w * wv.w;
        }
    }
#pragma unroll
    for (int off = 16; off > 0; off >>= 1)
#pragma unroll
        for (int t = 0; t < 4; t++)
#pragma unroll
            for (int e = 0; e < NEXP; e++)
                acc[t][e] += __shfl_down_sync(0xffffffffu, acc[t][e], off);

    if (lane == 0) {
#pragma unroll
        for (int t = 0; t < 4; t++) {
            int n = n0 + t;
            float l[NEXP];
#pragma unroll
            for (int e = 0; e < NEXP; e++) l[e] = tanhf(acc[t][e] + bg[e]);
            int i1 = 0; float b1 = l[0];
#pragma unroll
            for (int e = 1; e < NEXP; e++) if (l[e] > b1) { b1 = l[e]; i1 = e; }
            int i2 = -1; float b2 = -1e30f;
#pragma unroll
            for (int e = 0; e < NEXP; e++)
                if (e != i1 && l[e] > b2) { b2 = l[e]; i2 = e; }
            float ex  = expf(b2 - b1);
            float inv = 1.0f / (1.0f + ex);
            g_topE[n * 2 + 0] = i1;  g_topG[n * 2 + 0] = inv;
            g_topE[n * 2 + 1] = i2;  g_topG[n * 2 + 1] = ex * inv;
            atomicAdd(&g_cnt[i1], 1);
            atomicAdd(&g_cnt[i2], 1);
        }
    }
}

// Warp-aggregated scatter into fixed per-expert segments.
__global__ void scatter_kernel() {
    int idx  = blockIdx.x * 256 + threadIdx.x;
    int lane = threadIdx.x & 31;
    int e = g_topE[idx];
    unsigned mask = __match_any_sync(0xffffffffu, e);
    int leader = __ffs(mask) - 1;
    int rank   = __popc(mask & ((1u << lane) - 1));
    int basep = 0;
    if (lane == leader) basep = atomicAdd(&g_cur[e], __popc(mask));
    basep = __shfl_sync(0xffffffffu, basep, leader);
    int s = e * NTOK + basep + rank;
    g_tok[s] = idx >> 1;
    g_ki[s]  = idx & 1;
}

// --------------------------- grouped GEMM ------------------------------------
// Static grid: 8 experts x 256 tiles x 8 nb; early exit on count.
// CTA: 128x128, 256 threads = 8 warps (4M x 2N), warp tile 32x64.
// K=1024 in 16 chunks of 64, 3-stage cp.async manually unrolled x3.

constexpr int A_BYTES = TILE_M * KC * 2;   // 16 KB
constexpr int B_BYTES = NB * KC * 2;       // 16 KB
constexpr int STAGE   = A_BYTES + B_BYTES; // 32 KB
constexpr int DYN_SMEM = 3 * STAGE + 1024; // 99 KB -> 2 CTAs/SM

extern __shared__ __align__(1024) char dsm[];

__global__ void __launch_bounds__(256, 2)
moe_gemm_kernel(const float* __restrict__ be) {
    int bx  = blockIdx.x;
    int e   = bx >> 11;
    int rem = bx & 2047;
    int t   = rem >> 3;
    int nb  = rem & 7;

    int cnt  = g_cnt[e];
    int rows = cnt - t * TILE_M;
    if (rows <= 0) return;
    if (rows > TILE_M) rows = TILE_M;

    __shared__ int sTok[TILE_M];
    __shared__ int sKi[TILE_M];

    int tid  = threadIdx.x;
    int lane = tid & 31;
    int wid  = tid >> 5;
    int warpM = wid & 3;
    int warpN = wid >> 2;

    const int* segT = g_tok + e * NTOK + t * TILE_M;
    const int* segK = g_ki  + e * NTOK + t * TILE_M;
    if (tid < TILE_M) {
        int i = tid;
        int j = (i < rows ? i : rows - 1);
        sTok[i] = segT[j];
        sKi[i]  = segK[j];
    }
    __syncthreads();

    uint32_t base = (smem_u32(dsm) + 1023) & ~1023u;
    const __half* btBase = g_Bh + ((size_t)e * DOUT + nb * NB) * DIN;

    int r0 = tid >> 3;
    int ch = tid & 7;
    const __half* aP0 = g_xh + (size_t)sTok[r0 +  0] * DIN + ch * 8;
    const __half* aP1 = g_xh + (size_t)sTok[r0 + 32] * DIN + ch * 8;
    const __half* aP2 = g_xh + (size_t)sTok[r0 + 64] * DIN + ch * 8;
    const __half* aP3 = g_xh + (size_t)sTok[r0 + 96] * DIN + ch * 8;
    const __half* bP  = btBase + (size_t)r0 * DIN + ch * 8;
    uint32_t sOff = sw128((uint32_t)(r0 * 128 + ch * 16));

    float c[2][8][4];
#pragma unroll
    for (int mt = 0; mt < 2; mt++)
#pragma unroll
        for (int nt = 0; nt < 8; nt++)
#pragma unroll
            for (int q = 0; q < 4; q++) c[mt][nt][q] = 0.f;

    auto load_chunk = [&](uint32_t buf, int kg) {
        uint32_t aBuf = buf + sOff;
        uint32_t bBuf = buf + A_BYTES + sOff;
        cpa16(aBuf,         aP0 + kg);
        cpa16(aBuf +  4096, aP1 + kg);
        cpa16(aBuf +  8192, aP2 + kg);
        cpa16(aBuf + 12288, aP3 + kg);
        cpa16(bBuf,         bP + kg);
        cpa16(bBuf +  4096, bP + 32 * DIN + kg);
        cpa16(bBuf +  8192, bP + 64 * DIN + kg);
        cpa16(bBuf + 12288, bP + 96 * DIN + kg);
    };

    load_chunk(base, 0);
    CPA_COMMIT();
    load_chunk(base + STAGE, KC);
    CPA_COMMIT();

    uint32_t aRowOff = (uint32_t)((warpM * 32 + (lane & 15)) * 128 + ((lane >> 4) << 4));
    uint32_t bRowOff = (uint32_t)((warpN * 64 + (lane & 7) + ((lane >> 4) << 3)) * 128
                                  + (((lane >> 3) & 1) << 4));
    uint32_t aSwK[4], bSwK[4];
#pragma unroll
    for (int s4 = 0; s4 < 4; s4++) {
        aSwK[s4] = sw128(aRowOff + 32u * s4);
        bSwK[s4] = sw128(bRowOff + 32u * s4);
    }

    auto chunk_body = [&](int ck, int bufSel) {
        CPA_WAIT1();
        __syncthreads();
        if (ck + 2 < NCHUNK) {
            int nxt = (ck + 2) % 3;
            load_chunk(base + nxt * STAGE, (ck + 2) * KC);
        }
        CPA_COMMIT();

        uint32_t stageA = base + bufSel * STAGE;
        uint32_t stageB = stageA + A_BYTES;
#pragma unroll
        for (int s4 = 0; s4 < 4; s4++) {
            uint32_t aA = stageA + aSwK[s4];
            uint32_t bA = stageB + bSwK[s4];
            uint32_t aF[2][4], bF[4][4];
            ldsm4(aF[0][0], aF[0][1], aF[0][2], aF[0][3], aA);
            ldsm4(aF[1][0], aF[1][1], aF[1][2], aF[1][3], aA + 2048);
            ldsm4(bF[0][0], bF[0][1], bF[0][2], bF[0][3], bA);
            ldsm4(bF[1][0], bF[1][1], bF[1][2], bF[1][3], bA + 2048);
            ldsm4(bF[2][0], bF[2][1], bF[2][2], bF[2][3], bA + 4096);
            ldsm4(bF[3][0], bF[3][1], bF[3][2], bF[3][3], bA + 6144);
#pragma unroll
            for (int bt = 0; bt < 4; bt++) {
                mma16816(c[0][2 * bt],     aF[0][0], aF[0][1], aF[0][2], aF[0][3],
                         bF[bt][0], bF[bt][1]);
                mma16816(c[0][2 * bt + 1], aF[0][0], aF[0][1], aF[0][2], aF[0][3],
                         bF[bt][2], bF[bt][3]);
                mma16816(c[1][2 * bt],     aF[1][0], aF[1][1], aF[1][2], aF[1][3],
                         bF[bt][0], bF[bt][1]);
                mma16816(c[1][2 * bt + 1], aF[1][0], aF[1][1], aF[1][2], aF[1][3],
                         bF[bt][2], bF[bt][3]);
            }
        }
    };

#pragma unroll
    for (int c3 = 0; c3 < 15; c3 += 3) {
        chunk_body(c3,     0);
        chunk_body(c3 + 1, 1);
        chunk_body(c3 + 2, 2);
    }
    chunk_body(15, 0);

    // ---------------- epilogue: bias + GELU, write h (fp16) -------------------
    int la4 = lane >> 2, lq = lane & 3;
    int gcol0 = nb * NB + warpN * 64;

#pragma unroll
    for (int mt = 0; mt < 2; mt++) {
        int rr0 = warpM * 32 + mt * 16 + la4;
        int rr1 = rr0 + 8;
        bool v0 = rr0 < rows, v1 = rr1 < rows;
        __half* d0 = g_h + (((size_t)sTok[rr0] * 2 + sKi[rr0]) << 10);
        __half* d1 = g_h + (((size_t)sTok[rr1] * 2 + sKi[rr1]) << 10);
#pragma unroll
        for (int nt = 0; nt < 8; nt++) {
            int col = gcol0 + nt * 8 + 2 * lq;
            float2 bv = *(const float2*)(be + (size_t)e * DOUT + col);
            if (v0) {
                __half2 o = __floats2half2_rn(gelu_exact(c[mt][nt][0] + bv.x),
                                              gelu_exact(c[mt][nt][1] + bv.y));
                *(__half2*)(d0 + col) = o;
            }
            if (v1) {
                __half2 o = __floats2half2_rn(gelu_exact(c[mt][nt][2] + bv.x),
                                              gelu_exact(c[mt][nt][3] + bv.y));
                *(__half2*)(d1 + col) = o;
            }
        }
    }
}

// --------------- pass 2: LayerNorm + gamma/beta + gate + combine -------------
// 256 threads, 64 tokens/block (8 warps x 8 tokens serial), grid 512 for
// smoother SM load spread; gamma/beta staged once per block in 64 KB smem.
__global__ void __launch_bounds__(256)
ln_combine_kernel(const float* __restrict__ gamma,
                  const float* __restrict__ beta,
                  float* __restrict__ out) {
    float* gsm = (float*)dsm;            // [0:8192) gamma, [8192:16384) beta
    int tid = threadIdx.x;
    for (int i = tid; i < NEXP * DOUT; i += 256) {
        gsm[i]               = gamma[i];
        gsm[NEXP * DOUT + i] = beta[i];
    }
    __syncthreads();

    int wid = tid >> 5, lane = tid & 31;
    const float4* g4 = (const float4*)gsm;
    const float4* b4 = g4 + (NEXP * DOUT / 4);

    for (int t = 0; t < 8; t++) {
        int n = blockIdx.x * 64 + wid * 8 + t;

        const uint2* h0p = (const uint2*)(g_h + ((size_t)n * 2)     * DOUT);
        const uint2* h1p = (const uint2*)(g_h + ((size_t)n * 2 + 1) * DOUT);

        uint2 u0[8], u1[8];
        float s0 = 0.f, q0 = 0.f, s1 = 0.f, q1 = 0.f;
#pragma unroll
        for (int k = 0; k < 8; k++) {
            int cc = lane + 32 * k;
            u0[k] = h0p[cc];
            u1[k] = h1p[cc];
            float2 a0 = __half22float2(*(__half2*)&u0[k].x);
            float2 c0 = __half22float2(*(__half2*)&u0[k].y);
            float2 a1 = __half22float2(*(__half2*)&u1[k].x);
            float2 c1 = __half22float2(*(__half2*)&u1[k].y);
            s0 += a0.x + a0.y + c0.x + c0.y;
            q0 += a0.x * a0.x + a0.y * a0.y + c0.x * c0.x + c0.y * c0.y;
            s1 += a1.x + a1.y + c1.x + c1.y;
            q1 += a1.x * a1.x + a1.y * a1.y + c1.x * c1.x + c1.y * c1.y;
        }
#pragma unroll
        for (int off = 16; off > 0; off >>= 1) {
            s0 += __shfl_xor_sync(0xffffffffu, s0, off);
            q0 += __shfl_xor_sync(0xffffffffu, q0, off);
            s1 += __shfl_xor_sync(0xffffffffu, s1, off);
            q1 += __shfl_xor_sync(0xffffffffu, q1, off);
        }
        float m0 = s0 * (1.f / DOUT), m1 = s1 * (1.f / DOUT);
        float r0 = rsqrtf(q0 * (1.f / DOUT) - m0 * m0 + 1e-5f);
        float r1 = rsqrtf(q1 * (1.f / DOUT) - m1 * m1 + 1e-5f);

        int e0 = g_topE[n * 2 + 0], e1 = g_topE[n * 2 + 1];
        float gg0 = g_topG[n * 2 + 0], gg1 = g_topG[n * 2 + 1];
        int gi0 = e0 * (DOUT / 4), gi1 = e1 * (DOUT / 4);

        float4* op = (float4*)out + (size_t)n * (DOUT / 4);
#pragma unroll
        for (int k = 0; k < 8; k++) {
            int cc = lane + 32 * k;
            float2 a0 = __half22float2(*(__half2*)&u0[k].x);
            float2 c0 = __half22float2(*(__half2*)&u0[k].y);
            float2 a1 = __half22float2(*(__half2*)&u1[k].x);
            float2 c1 = __half22float2(*(__half2*)&u1[k].y);
            float4 ga = g4[gi0 + cc], ba = b4[gi0 + cc];
            float4 gb = g4[gi1 + cc], bb = b4[gi1 + cc];
            float4 o;
            o.x = ((a0.x - m0) * r0 * ga.x + ba.x) * gg0 + ((a1.x - m1) * r1 * gb.x + bb.x) * gg1;
            o.y = ((a0.y - m0) * r0 * ga.y + ba.y) * gg0 + ((a1.y - m1) * r1 * gb.y + bb.y) * gg1;
            o.z = ((c0.x - m0) * r0 * ga.z + ba.z) * gg0 + ((c1.x - m1) * r1 * gb.z + bb.z) * gg1;
            o.w = ((c0.y - m0) * r0 * ga.w + ba.w) * gg0 + ((c1.y - m1) * r1 * gb.w + bb.w) * gg1;
            op[cc] = o;
        }
    }
}

// ------------------------------- launcher -----------------------------------
extern "C" void kernel_launch(void* const* d_in, const int* in_sizes, int n_in,
                              void* d_out, int out_size) {
    const float* x     = (const float*)d_in[0];
    const float* Wg    = (const float*)d_in[1];
    const float* bg    = (const float*)d_in[2];
    const float* We    = (const float*)d_in[3];
    const float* be    = (const float*)d_in[4];
    const float* gamma = (const float*)d_in[5];
    const float* beta  = (const float*)d_in[6];
    float* out = (float*)d_out;

    cudaFuncSetAttribute(moe_gemm_kernel,
                         cudaFuncAttributeMaxDynamicSharedMemorySize, DYN_SMEM);
    cudaFuncSetAttribute(ln_combine_kernel,
                         cudaFuncAttributeMaxDynamicSharedMemorySize, 65536);

    transpose_kernel<<<dim3(32, 32, 8), dim3(32, 8)>>>(We);   // + counter zeroing
    xgate_kernel<<<NTOK / 32, 256>>>(x, Wg, bg);
    scatter_kernel<<<NASSIGN / 256, 256>>>();
    moe_gemm_kernel<<<NEXP * TPE * NNB, 256, DYN_SMEM>>>(be); // 4th -> profiled
    ln_combine_kernel<<<NTOK / 64, 256, 65536>>>(gamma, beta, out);
}

// round 16
// speedup vs baseline: 1.0729x; 1.0508x over previous
#include <cuda_runtime.h>
#include <cuda_fp16.h>
#include <cstdint>

// ---------------------------------------------------------------------------
// MoE top-2/8, sparse routing. GEMM: mma.sync.m16n8k16.f16 (fp32 accum),
// ldmatrix, 3-stage cp.async pipeline (unrolled x3), CTA 128x128, 2 CTAs/SM.
// R16 (on R13 base): xgate tail parallelized across lanes 0-3 (reduction
// order preserved -> bit-identical routing); transpose split into 3 launches
// so xgate occupies the profiled 4th slot.
// ---------------------------------------------------------------------------

#define NTOK   32768
#define DIN    1024
#define DOUT   1024
#define NEXP   8
#define NASSIGN (NTOK * 2)
#define TILE_M 128
#define TPE    (NTOK / TILE_M)     // 256 max tiles per expert
#define KC     64
#define NB     128
#define NNB    (DOUT / NB)         // 8
#define NCHUNK (DIN / KC)          // 16

// ---------------- scratch (device globals: allocation-free) ----------------
__device__ int    g_topE[NASSIGN];
__device__ float  g_topG[NASSIGN];
__device__ int    g_cnt[NEXP];
__device__ int    g_cur[NEXP];
__device__ int    g_tok[NEXP * NTOK];
__device__ int    g_ki[NEXP * NTOK];
__device__ __half g_xh[(size_t)NTOK * DIN];            // fp16 x (64 MB)
__device__ __half g_Bh[(size_t)NEXP * DOUT * DIN];     // W^T fp16 [e][n][k] (16 MB)
__device__ __half g_h[(size_t)NASSIGN * DOUT];         // GELU(xW+b) fp16 (128 MB)

// ---------------------------- helpers ---------------------------------------
__device__ __forceinline__ float gelu_exact(float v) {
    return 0.5f * v * (1.0f + erff(v * 0.70710678118654752f));
}
__device__ __forceinline__ uint32_t smem_u32(const void* p) {
    uint32_t a;
    asm("{ .reg .u64 t; cvta.to.shared.u64 t, %1; cvt.u32.u64 %0, t; }"
        : "=r"(a) : "l"(p));
    return a;
}
__device__ __forceinline__ uint32_t sw128(uint32_t o) { return o ^ ((o >> 3) & 0x70); }

__device__ __forceinline__ void cpa16(uint32_t saddr, const void* g) {
    asm volatile("cp.async.cg.shared.global [%0], [%1], 16;\n"
                 :: "r"(saddr), "l"(g));
}
#define CPA_COMMIT() asm volatile("cp.async.commit_group;\n" ::: "memory")
#define CPA_WAIT1()  asm volatile("cp.async.wait_group 1;\n" ::: "memory")

__device__ __forceinline__ void ldsm4(uint32_t& r0, uint32_t& r1,
                                      uint32_t& r2, uint32_t& r3, uint32_t a) {
    asm volatile("ldmatrix.sync.aligned.m8n8.x4.shared.b16 {%0,%1,%2,%3}, [%4];"
                 : "=r"(r0), "=r"(r1), "=r"(r2), "=r"(r3) : "r"(a));
}
__device__ __forceinline__ void mma16816(float (&c)[4],
                                         uint32_t a0, uint32_t a1,
                                         uint32_t a2, uint32_t a3,
                                         uint32_t b0, uint32_t b1) {
    asm volatile(
        "mma.sync.aligned.m16n8k16.row.col.f32.f16.f16.f32 "
        "{%0,%1,%2,%3},{%4,%5,%6,%7},{%8,%9},{%0,%1,%2,%3};\n"
        : "+f"(c[0]), "+f"(c[1]), "+f"(c[2]), "+f"(c[3])
        : "r"(a0), "r"(a1), "r"(a2), "r"(a3), "r"(b0), "r"(b1));
}

// ------------------------------- kernels -------------------------------------

// We[e][k][n] (fp32) -> g_Bh[e][n][k] (fp16) for experts [e0, e0+gridDim.z).
// First launch (e0==0) block(0,0,0) also zeroes the routing counters.
__global__ void transpose_kernel(const float* __restrict__ We, int e0) {
    if (e0 == 0 && blockIdx.x == 0 && blockIdx.y == 0 && blockIdx.z == 0 &&
        threadIdx.y == 0 && threadIdx.x < NEXP) {
        g_cnt[threadIdx.x] = 0;
        g_cur[threadIdx.x] = 0;
    }
    __shared__ float tile[32][33];
    int e  = e0 + blockIdx.z;
    int kb = blockIdx.y * 32;
    int nb = blockIdx.x * 32;
    const float* src = We + ((size_t)e * DIN + kb) * DOUT + nb;
#pragma unroll
    for (int i = 0; i < 32; i += 8)
        tile[threadIdx.y + i][threadIdx.x] = src[(size_t)(threadIdx.y + i) * DOUT + threadIdx.x];
    __syncthreads();
    __half* dst = g_Bh + ((size_t)e * DOUT + nb) * DIN + kb;
#pragma unroll
    for (int i = 0; i < 32; i += 8)
        dst[(size_t)(threadIdx.y + i) * DIN + threadIdx.x] =
            __float2half_rn(tile[threadIdx.x][threadIdx.y + i]);
}

// --------------------- fused x->fp16 + gating (fp32) -------------------------
// 4 tokens per warp (Wg smem read reused 4x). Reduction via shfl_down to lane
// 0 (bit-identical to R13), then lane-0 sums broadcast so lanes 0-3 process
// one token each in parallel (tail was serialized on lane 0 before).
__global__ void __launch_bounds__(256)
xgate_kernel(const float* __restrict__ x,
             const float* __restrict__ Wg,
             const float* __restrict__ bg) {
    __shared__ float sW[NEXP][DIN];   // 32 KB transposed: sW[e][i]
    int tid = threadIdx.x;
    for (int idx = tid; idx < DIN * NEXP; idx += 256) {
        int i = idx >> 3, e = idx & 7;
        sW[e][i] = Wg[idx];
    }
    __syncthreads();

    int wid = tid >> 5, lane = tid & 31;
    int n0 = blockIdx.x * 32 + wid * 4;

    const float4* xr = (const float4*)(x + (size_t)n0 * DIN);
    uint2*        xo = (uint2*)(g_xh + (size_t)n0 * DIN);

    float acc[4][NEXP];
#pragma unroll
    for (int t = 0; t < 4; t++)
#pragma unroll
        for (int e = 0; e < NEXP; e++) acc[t][e] = 0.f;

#pragma unroll
    for (int j = 0; j < 8; j++) {
        int c = lane + 32 * j;
        float4 xv[4];
#pragma unroll
        for (int t = 0; t < 4; t++) {
            xv[t] = xr[t * 256 + c];
            __half2 h01 = __floats2half2_rn(xv[t].x, xv[t].y);
            __half2 h23 = __floats2half2_rn(xv[t].z, xv[t].w);
            uint2 o;
            o.x = *(uint32_t*)&h01;
            o.y = *(uint32_t*)&h23;
            xo[t * 256 + c] = o;
        }
#pragma unroll
        for (int e = 0; e < NEXP; e++) {
            float4 wv = ((const float4*)sW[e])[c];
#pragma unroll
            for (int t = 0; t < 4; t++)
                acc[t][e] += xv[t].x * wv.x + xv[t].y * wv.y
                           + xv[t].z * wv.z + xv[t].w * wv.w;
        }
    }
    // order-preserving reduction (identical to R13)
#pragma unroll
    for (int off = 16; off > 0; off >>= 1)
#pragma unroll
        for (int t = 0; t < 4; t++)
#pragma unroll
            for (int e = 0; e < NEXP; e++)
                acc[t][e] += __shfl_down_sync(0xffffffffu, acc[t][e], off);

    // broadcast lane-0 totals; lanes 0-3 handle one token each (parallel tail)
#pragma unroll
    for (int t = 0; t < 4; t++)
#pragma unroll
        for (int e = 0; e < NEXP; e++)
            acc[t][e] = __shfl_sync(0xffffffffu, acc[t][e], 0);

    if (lane < 4) {
        int t = lane;
        int n = n0 + t;
        float l[NEXP];
#pragma unroll
        for (int e = 0; e < NEXP; e++) l[e] = tanhf(acc[t][e] + bg[e]);
        int i1 = 0; float b1 = l[0];
#pragma unroll
        for (int e = 1; e < NEXP; e++) if (l[e] > b1) { b1 = l[e]; i1 = e; }
        int i2 = -1; float b2 = -1e30f;
#pragma unroll
        for (int e = 0; e < NEXP; e++)
            if (e != i1 && l[e] > b2) { b2 = l[e]; i2 = e; }
        float ex  = expf(b2 - b1);
        float inv = 1.0f / (1.0f + ex);
        g_topE[n * 2 + 0] = i1;  g_topG[n * 2 + 0] = inv;
        g_topE[n * 2 + 1] = i2;  g_topG[n * 2 + 1] = ex * inv;
        atomicAdd(&g_cnt[i1], 1);
        atomicAdd(&g_cnt[i2], 1);
    }
}

// Warp-aggregated scatter into fixed per-expert segments.
__global__ void scatter_kernel() {
    int idx  = blockIdx.x * 256 + threadIdx.x;
    int lane = threadIdx.x & 31;
    int e = g_topE[idx];
    unsigned mask = __match_any_sync(0xffffffffu, e);
    int leader = __ffs(mask) - 1;
    int rank   = __popc(mask & ((1u << lane) - 1));
    int basep = 0;
    if (lane == leader) basep = atomicAdd(&g_cur[e], __popc(mask));
    basep = __shfl_sync(0xffffffffu, basep, leader);
    int s = e * NTOK + basep + rank;
    g_tok[s] = idx >> 1;
    g_ki[s]  = idx & 1;
}

// --------------------------- grouped GEMM ------------------------------------
// Static grid: 8 experts x 256 tiles x 8 nb; early exit on count.
// CTA: 128x128, 256 threads = 8 warps (4M x 2N), warp tile 32x64.
// K=1024 in 16 chunks of 64, 3-stage cp.async manually unrolled x3.

constexpr int A_BYTES = TILE_M * KC * 2;   // 16 KB
constexpr int B_BYTES = NB * KC * 2;       // 16 KB
constexpr int STAGE   = A_BYTES + B_BYTES; // 32 KB
constexpr int DYN_SMEM = 3 * STAGE + 1024; // 99 KB -> 2 CTAs/SM

extern __shared__ __align__(1024) char dsm[];

__global__ void __launch_bounds__(256, 2)
moe_gemm_kernel(const float* __restrict__ be) {
    int bx  = blockIdx.x;
    int e   = bx >> 11;
    int rem = bx & 2047;
    int t   = rem >> 3;
    int nb  = rem & 7;

    int cnt  = g_cnt[e];
    int rows = cnt - t * TILE_M;
    if (rows <= 0) return;
    if (rows > TILE_M) rows = TILE_M;

    __shared__ int sTok[TILE_M];
    __shared__ int sKi[TILE_M];

    int tid  = threadIdx.x;
    int lane = tid & 31;
    int wid  = tid >> 5;
    int warpM = wid & 3;
    int warpN = wid >> 2;

    const int* segT = g_tok + e * NTOK + t * TILE_M;
    const int* segK = g_ki  + e * NTOK + t * TILE_M;
    if (tid < TILE_M) {
        int i = tid;
        int j = (i < rows ? i : rows - 1);
        sTok[i] = segT[j];
        sKi[i]  = segK[j];
    }
    __syncthreads();

    uint32_t base = (smem_u32(dsm) + 1023) & ~1023u;
    const __half* btBase = g_Bh + ((size_t)e * DOUT + nb * NB) * DIN;

    int r0 = tid >> 3;
    int ch = tid & 7;
    const __half* aP0 = g_xh + (size_t)sTok[r0 +  0] * DIN + ch * 8;
    const __half* aP1 = g_xh + (size_t)sTok[r0 + 32] * DIN + ch * 8;
    const __half* aP2 = g_xh + (size_t)sTok[r0 + 64] * DIN + ch * 8;
    const __half* aP3 = g_xh + (size_t)sTok[r0 + 96] * DIN + ch * 8;
    const __half* bP  = btBase + (size_t)r0 * DIN + ch * 8;
    uint32_t sOff = sw128((uint32_t)(r0 * 128 + ch * 16));

    float c[2][8][4];
#pragma unroll
    for (int mt = 0; mt < 2; mt++)
#pragma unroll
        for (int nt = 0; nt < 8; nt++)
#pragma unroll
            for (int q = 0; q < 4; q++) c[mt][nt][q] = 0.f;

    auto load_chunk = [&](uint32_t buf, int kg) {
        uint32_t aBuf = buf + sOff;
        uint32_t bBuf = buf + A_BYTES + sOff;
        cpa16(aBuf,         aP0 + kg);
        cpa16(aBuf +  4096, aP1 + kg);
        cpa16(aBuf +  8192, aP2 + kg);
        cpa16(aBuf + 12288, aP3 + kg);
        cpa16(bBuf,         bP + kg);
        cpa16(bBuf +  4096, bP + 32 * DIN + kg);
        cpa16(bBuf +  8192, bP + 64 * DIN + kg);
        cpa16(bBuf + 12288, bP + 96 * DIN + kg);
    };

    load_chunk(base, 0);
    CPA_COMMIT();
    load_chunk(base + STAGE, KC);
    CPA_COMMIT();

    uint32_t aRowOff = (uint32_t)((warpM * 32 + (lane & 15)) * 128 + ((lane >> 4) << 4));
    uint32_t bRowOff = (uint32_t)((warpN * 64 + (lane & 7) + ((lane >> 4) << 3)) * 128
                                  + (((lane >> 3) & 1) << 4));
    uint32_t aSwK[4], bSwK[4];
#pragma unroll
    for (int s4 = 0; s4 < 4; s4++) {
        aSwK[s4] = sw128(aRowOff + 32u * s4);
        bSwK[s4] = sw128(bRowOff + 32u * s4);
    }

    auto chunk_body = [&](int ck, int bufSel) {
        CPA_WAIT1();
        __syncthreads();
        if (ck + 2 < NCHUNK) {
            int nxt = (ck + 2) % 3;
            load_chunk(base + nxt * STAGE, (ck + 2) * KC);
        }
        CPA_COMMIT();

        uint32_t stageA = base + bufSel * STAGE;
        uint32_t stageB = stageA + A_BYTES;
#pragma unroll
        for (int s4 = 0; s4 < 4; s4++) {
            uint32_t aA = stageA + aSwK[s4];
            uint32_t bA = stageB + bSwK[s4];
            uint32_t aF[2][4], bF[4][4];
            ldsm4(aF[0][0], aF[0][1], aF[0][2], aF[0][3], aA);
            ldsm4(aF[1][0], aF[1][1], aF[1][2], aF[1][3], aA + 2048);
            ldsm4(bF[0][0], bF[0][1], bF[0][2], bF[0][3], bA);
            ldsm4(bF[1][0], bF[1][1], bF[1][2], bF[1][3], bA + 2048);
            ldsm4(bF[2][0], bF[2][1], bF[2][2], bF[2][3], bA + 4096);
            ldsm4(bF[3][0], bF[3][1], bF[3][2], bF[3][3], bA + 6144);
#pragma unroll
            for (int bt = 0; bt < 4; bt++) {
                mma16816(c[0][2 * bt],     aF[0][0], aF[0][1], aF[0][2], aF[0][3],
                         bF[bt][0], bF[bt][1]);
                mma16816(c[0][2 * bt + 1], aF[0][0], aF[0][1], aF[0][2], aF[0][3],
                         bF[bt][2], bF[bt][3]);
                mma16816(c[1][2 * bt],     aF[1][0], aF[1][1], aF[1][2], aF[1][3],
                         bF[bt][0], bF[bt][1]);
                mma16816(c[1][2 * bt + 1], aF[1][0], aF[1][1], aF[1][2], aF[1][3],
                         bF[bt][2], bF[bt][3]);
            }
        }
    };

#pragma unroll
    for (int c3 = 0; c3 < 15; c3 += 3) {
        chunk_body(c3,     0);
        chunk_body(c3 + 1, 1);
        chunk_body(c3 + 2, 2);
    }
    chunk_body(15, 0);

    // ---------------- epilogue: bias + GELU, write h (fp16) -------------------
    int la4 = lane >> 2, lq = lane & 3;
    int gcol0 = nb * NB + warpN * 64;

#pragma unroll
    for (int mt = 0; mt < 2; mt++) {
        int rr0 = warpM * 32 + mt * 16 + la4;
        int rr1 = rr0 + 8;
        bool v0 = rr0 < rows, v1 = rr1 < rows;
        __half* d0 = g_h + (((size_t)sTok[rr0] * 2 + sKi[rr0]) << 10);
        __half* d1 = g_h + (((size_t)sTok[rr1] * 2 + sKi[rr1]) << 10);
#pragma unroll
        for (int nt = 0; nt < 8; nt++) {
            int col = gcol0 + nt * 8 + 2 * lq;
            float2 bv = *(const float2*)(be + (size_t)e * DOUT + col);
            if (v0) {
                __half2 o = __floats2half2_rn(gelu_exact(c[mt][nt][0] + bv.x),
                                              gelu_exact(c[mt][nt][1] + bv.y));
                *(__half2*)(d0 + col) = o;
            }
            if (v1) {
                __half2 o = __floats2half2_rn(gelu_exact(c[mt][nt][2] + bv.x),
                                              gelu_exact(c[mt][nt][3] + bv.y));
                *(__half2*)(d1 + col) = o;
            }
        }
    }
}

// --------------- pass 2: LayerNorm + gamma/beta + gate + combine -------------
// 256 threads, 128 tokens/block (8 warps x 16 tokens serial); gamma/beta
// staged once per block in 64 KB smem (R13 proven shape).
__global__ void __launch_bounds__(256)
ln_combine_kernel(const float* __restrict__ gamma,
                  const float* __restrict__ beta,
                  float* __restrict__ out) {
    float* gsm = (float*)dsm;            // [0:8192) gamma, [8192:16384) beta
    int tid = threadIdx.x;
    for (int i = tid; i < NEXP * DOUT; i += 256) {
        gsm[i]               = gamma[i];
        gsm[NEXP * DOUT + i] = beta[i];
    }
    __syncthreads();

    int wid = tid >> 5, lane = tid & 31;
    const float4* g4 = (const float4*)gsm;
    const float4* b4 = g4 + (NEXP * DOUT / 4);

    for (int t = 0; t < 16; t++) {
        int n = blockIdx.x * 128 + wid * 16 + t;

        const uint2* h0p = (const uint2*)(g_h + ((size_t)n * 2)     * DOUT);
        const uint2* h1p = (const uint2*)(g_h + ((size_t)n * 2 + 1) * DOUT);

        uint2 u0[8], u1[8];
        float s0 = 0.f, q0 = 0.f, s1 = 0.f, q1 = 0.f;
#pragma unroll
        for (int k = 0; k < 8; k++) {
            int cc = lane + 32 * k;
            u0[k] = h0p[cc];
            u1[k] = h1p[cc];
            float2 a0 = __half22float2(*(__half2*)&u0[k].x);
            float2 c0 = __half22float2(*(__half2*)&u0[k].y);
            float2 a1 = __half22float2(*(__half2*)&u1[k].x);
            float2 c1 = __half22float2(*(__half2*)&u1[k].y);
            s0 += a0.x + a0.y + c0.x + c0.y;
            q0 += a0.x * a0.x + a0.y * a0.y + c0.x * c0.x + c0.y * c0.y;
            s1 += a1.x + a1.y + c1.x + c1.y;
            q1 += a1.x * a1.x + a1.y * a1.y + c1.x * c1.x + c1.y * c1.y;
        }
#pragma unroll
        for (int off = 16; off > 0; off >>= 1) {
            s0 += __shfl_xor_sync(0xffffffffu, s0, off);
            q0 += __shfl_xor_sync(0xffffffffu, q0, off);
            s1 += __shfl_xor_sync(0xffffffffu, s1, off);
            q1 += __shfl_xor_sync(0xffffffffu, q1, off);
        }
        float m0 = s0 * (1.f / DOUT), m1 = s1 * (1.f / DOUT);
        float r0 = rsqrtf(q0 * (1.f / DOUT) - m0 * m0 + 1e-5f);
        float r1 = rsqrtf(q1 * (1.f / DOUT) - m1 * m1 + 1e-5f);

        int e0 = g_topE[n * 2 + 0], e1 = g_topE[n * 2 + 1];
        float gg0 = g_topG[n * 2 + 0], gg1 = g_topG[n * 2 + 1];
        int gi0 = e0 * (DOUT / 4), gi1 = e1 * (DOUT / 4);

        float4* op = (float4*)out + (size_t)n * (DOUT / 4);
#pragma unroll
        for (int k = 0; k < 8; k++) {
            int cc = lane + 32 * k;
            float2 a0 = __half22float2(*(__half2*)&u0[k].x);
            float2 c0 = __half22float2(*(__half2*)&u0[k].y);
            float2 a1 = __half22float2(*(__half2*)&u1[k].x);
            float2 c1 = __half22float2(*(__half2*)&u1[k].y);
            float4 ga = g4[gi0 + cc], ba = b4[gi0 + cc];
            float4 gb = g4[gi1 + cc], bb = b4[gi1 + cc];
            float4 o;
            o.x = ((a0.x - m0) * r0 * ga.x + ba.x) * gg0 + ((a1.x - m1) * r1 * gb.x + bb.x) * gg1;
            o.y = ((a0.y - m0) * r0 * ga.y + ba.y) * gg0 + ((a1.y - m1) * r1 * gb.y + bb.y) * gg1;
            o.z = ((c0.x - m0) * r0 * ga.z + ba.z) * gg0 + ((c1.x - m1) * r1 * gb.z + bb.z) * gg1;
            o.w = ((c0.y - m0) * r0 * ga.w + ba.w) * gg0 + ((c1.y - m1) * r1 * gb.w + bb.w) * gg1;
            op[cc] = o;
        }
    }
}

// ------------------------------- launcher -----------------------------------
extern "C" void kernel_launch(void* const* d_in, const int* in_sizes, int n_in,
                              void* d_out, int out_size) {
    const float* x     = (const float*)d_in[0];
    const float* Wg    = (const float*)d_in[1];
    const float* bg    = (const float*)d_in[2];
    const float* We    = (const float*)d_in[3];
    const float* be    = (const float*)d_in[4];
    const float* gamma = (const float*)d_in[5];
    const float* beta  = (const float*)d_in[6];
    float* out = (float*)d_out;

    cudaFuncSetAttribute(moe_gemm_kernel,
                         cudaFuncAttributeMaxDynamicSharedMemorySize, DYN_SMEM);
    cudaFuncSetAttribute(ln_combine_kernel,
                         cudaFuncAttributeMaxDynamicSharedMemorySize, 65536);

    // transpose split into 3 launches (experts 0-2, 3-5, 6-7) so xgate is the
    // profiled 4th launch; first launch zeroes the routing counters.
    transpose_kernel<<<dim3(32, 32, 3), dim3(32, 8)>>>(We, 0);
    transpose_kernel<<<dim3(32, 32, 3), dim3(32, 8)>>>(We, 3);
    transpose_kernel<<<dim3(32, 32, 2), dim3(32, 8)>>>(We, 6);
    xgate_kernel<<<NTOK / 32, 256>>>(x, Wg, bg);              // 4th -> profiled
    scatter_kernel<<<NASSIGN / 256, 256>>>();
    moe_gemm_kernel<<<NEXP * TPE * NNB, 256, DYN_SMEM>>>(be);
    ln_combine_kernel<<<NTOK / 128, 256, 65536>>>(gamma, beta, out);
}